// round 10
// baseline (speedup 1.0000x reference)
#include <cuda_runtime.h>
#include <cstdint>

// Optical 4f FFT "conv" == real 9x9 circular convolution:
//   out[b,o,i,j] = sum_c | sum_{a,t<9} K[o,0,a,t] * x[b,c,(i+5-a)&127,(j+5-t)&127] |
// B=8, C=16, H=W=128, O=32, ks=9.
//
// R9: R6 structure (single x copy, odd-tap pairs via register half-merge)
// but __launch_bounds__(128, 3): 3 CTAs/SM -> reg budget 170, so ptxas keeps
// its natural ~145 regs and the R6 address-rematerialization storm (alu 39%)
// disappears, while keeping 12 warps/SM of latency hiding.

#define TW 32
#define TH 8
#define XCOLS 40       // TW + 8
#define XROWS 16       // TH + 8
#define NTHREADS 128
#define CPLANE (XROWS * XCOLS)          // 640
#define XS_FLOATS (16 * CPLANE)         // 10240
#define SMEM_BYTES (XS_FLOATS * 4 + 8 * 90 * 8)   // 40960 + 5760 = 46720

static __device__ __forceinline__ void ffma2(unsigned long long& d,
                                             unsigned long long a,
                                             unsigned long long b) {
    asm("fma.rn.f32x2 %0, %1, %2, %0;" : "+l"(d) : "l"(a), "l"(b));
}
static __device__ __forceinline__ unsigned long long fadd2(unsigned long long a,
                                                           unsigned long long b) {
    unsigned long long d;
    asm("add.rn.f32x2 %0, %1, %2;" : "=l"(d) : "l"(a), "l"(b));
    return d;
}
// pair {hi(a), lo(b)} — register half selection + one mov.b64
static __device__ __forceinline__ unsigned long long merge_hl(unsigned long long a,
                                                              unsigned long long b) {
    unsigned int ah = (unsigned int)(a >> 32);
    unsigned int bl = (unsigned int)b;
    unsigned long long d;
    asm("mov.b64 %0, {%1, %2};" : "=l"(d) : "r"(ah), "r"(bl));
    return d;
}

__global__ void __launch_bounds__(NTHREADS, 3)
optical_conv_kernel(const float* __restrict__ x,
                    const float* __restrict__ ker,
                    float* __restrict__ out) {
    extern __shared__ float sm[];
    float* xs = sm;                                                   // [16][XROWS][XCOLS]
    unsigned long long* w2 = reinterpret_cast<unsigned long long*>(sm + XS_FLOATS); // [8][90]

    const int tid = threadIdx.x;
    const int bx = blockIdx.x;       // 0..3   tile col
    const int by = blockIdx.y;       // 0..15  tile row
    const int bz = blockIdx.z;       // b*4 + og
    const int b  = bz >> 2;
    const int og = bz & 3;           // group of 8 output channels

    const int j0 = bx * TW;
    const int i0 = by * TH;

    // ---- stage x tile (all 16 channels, halo, circular wrap) ----
    const float* xb = x + b * (16 * 128 * 128);
    for (int idx = tid; idx < XS_FLOATS; idx += NTHREADS) {
        int c   = idx / CPLANE;
        int rem = idx - c * CPLANE;
        int r   = rem / XCOLS;
        int m   = rem - r * XCOLS;
        int gr  = (i0 - 3 + r) & 127;
        int gc  = (j0 - 3 + m) & 127;
        xs[idx] = xb[(c * 128 + gr) * 128 + gc];
    }

    // ---- stage weights for this og: only kernel[o][0][...] matters ----
    const float* kb = ker + (og * 8) * (16 * 81);
    for (int idx = tid; idx < 8 * 81; idx += NTHREADS) {
        int o = idx / 81;
        int k = idx - o * 81;
        int a = k / 9;
        int t = k - a * 9;
        float w = kb[o * (16 * 81) + k];
        unsigned int wi = __float_as_uint(w);
        unsigned long long p;
        asm("mov.b64 %0, {%1, %1};" : "=l"(p) : "r"(wi));
        w2[o * 90 + a * 10 + t] = p;
    }
    __syncthreads();

    const int tx   = tid & 15;       // pixel-pair index
    const int ty   = tid >> 4;       // output row within tile
    const int colb = 2 * tx;

    unsigned long long acc[8];
    #pragma unroll
    for (int o = 0; o < 8; ++o) acc[o] = 0ull;

    for (int cg = 0; cg < 4; ++cg) {               // 4 channels per pass
        unsigned long long cv[8][4];
        #pragma unroll
        for (int o = 0; o < 8; ++o)
            #pragma unroll
            for (int c = 0; c < 4; ++c) cv[o][c] = 0ull;

        const float* xc = xs + cg * (4 * CPLANE);

        for (int a = 0; a < 9; ++a) {
            const int rowoff = (ty + 8 - a) * XCOLS + colb;
            const float* p0 = xc + rowoff;
            const unsigned long long* wr = w2 + a * 10;

            // aligned even-tap ulls: U[k] = floats {colb+2k, colb+2k+1}, k=0..4
            unsigned long long U[4][5];
            #pragma unroll
            for (int c = 0; c < 4; ++c)
                #pragma unroll
                for (int k = 0; k < 5; ++k)
                    U[c][k] = *reinterpret_cast<const unsigned long long*>(p0 + c * CPLANE + 2 * k);

            #pragma unroll
            for (int t0 = 0; t0 < 8; t0 += 2) {    // taps t0 (even), t0+1 (odd)
                const int ke = (8 - t0) / 2;       // even tap source
                // odd tap t0+1 pair = {hi(U[ke-1]), lo(U[ke])}
                unsigned long long xo[4];
                #pragma unroll
                for (int c = 0; c < 4; ++c)
                    xo[c] = merge_hl(U[c][ke - 1], U[c][ke]);

                #pragma unroll
                for (int o = 0; o < 8; ++o) {
                    ulonglong2 w01 = *reinterpret_cast<const ulonglong2*>(wr + o * 90 + t0);
                    #pragma unroll
                    for (int c = 0; c < 4; ++c) {
                        ffma2(cv[o][c], U[c][ke], w01.x);
                        ffma2(cv[o][c], xo[c],   w01.y);
                    }
                }
            }
            {   // tap t = 8 (even, U[0])
                #pragma unroll
                for (int o = 0; o < 8; ++o) {
                    unsigned long long w8 = wr[o * 90 + 8];
                    #pragma unroll
                    for (int c = 0; c < 4; ++c) ffma2(cv[o][c], U[c][0], w8);
                }
            }
        }

        // |field| summed over the 4 channels of this group
        #pragma unroll
        for (int o = 0; o < 8; ++o)
            #pragma unroll
            for (int c = 0; c < 4; ++c)
                acc[o] = fadd2(acc[o], cv[o][c] & 0x7FFFFFFF7FFFFFFFull);
    }

    // ---- store: out[b, og*8+o, i0+ty, j0+colb .. +1] ----
    const int i = i0 + ty;
    const int j = j0 + colb;
    float* ob = out + ((b * 32 + og * 8) * 128 + i) * 128 + j;
    #pragma unroll
    for (int o = 0; o < 8; ++o)
        *reinterpret_cast<unsigned long long*>(ob + o * (128 * 128)) = acc[o];
}

extern "C" void kernel_launch(void* const* d_in, const int* in_sizes, int n_in,
                              void* d_out, int out_size) {
    const float* x   = (const float*)d_in[0];   // [8,16,128,128]
    const float* ker = (const float*)d_in[1];   // [32,16,9,9]
    float* out = (float*)d_out;                 // [8,32,128,128]
    (void)in_sizes; (void)n_in; (void)out_size;

    cudaFuncSetAttribute(optical_conv_kernel,
                         cudaFuncAttributeMaxDynamicSharedMemorySize, SMEM_BYTES);

    dim3 grid(4, 16, 32);   // 4 col-tiles, 16 row-tiles, 8 batch * 4 o-groups
    optical_conv_kernel<<<grid, NTHREADS, SMEM_BYTES>>>(x, ker, out);
}

// round 11
// speedup vs baseline: 1.2599x; 1.2599x over previous
#include <cuda_runtime.h>
#include <cstdint>

// Optical 4f FFT "conv" == real 9x9 circular convolution:
//   out[b,o,i,j] = sum_c | sum_{a,t<9} K[o,0,a,t] * x[b,c,(i+5-a)&127,(j+5-t)&127] |
// B=8, C=16, H=W=128, O=32, ks=9.
//
// R10: back to the R5 datapath (plain + shifted smem copies; every tap pair is
// ONE aligned LDS.64, no register half-merges -> alu pipe stays ~12%), but the
// x tile is staged 8 channels at a time, halving smem to 46.7KB so 3 CTAs/SM
// (12 warps) hide LDS/FFMA latency instead of R5's 2 CTAs.

#define TW 32
#define TH 8
#define XCOLS 40       // TW + 8
#define XROWS 16       // TH + 8
#define NTHREADS 128
#define CPLANE (XROWS * XCOLS)          // 640
#define XS_HALF (8 * CPLANE)            // 5120 floats: 8 channels per half
#define SMEM_BYTES (2 * XS_HALF * 4 + 8 * 90 * 8)   // 40960 + 5760 = 46720

static __device__ __forceinline__ void ffma2(unsigned long long& d,
                                             unsigned long long a,
                                             unsigned long long b) {
    asm("fma.rn.f32x2 %0, %1, %2, %0;" : "+l"(d) : "l"(a), "l"(b));
}
static __device__ __forceinline__ unsigned long long fadd2(unsigned long long a,
                                                           unsigned long long b) {
    unsigned long long d;
    asm("add.rn.f32x2 %0, %1, %2;" : "=l"(d) : "l"(a), "l"(b));
    return d;
}

__global__ void __launch_bounds__(NTHREADS, 3)
optical_conv_kernel(const float* __restrict__ x,
                    const float* __restrict__ ker,
                    float* __restrict__ out) {
    extern __shared__ float sm[];
    float* xs  = sm;                  // [8][XROWS][XCOLS] current half, plain
    float* xsh = sm + XS_HALF;        // shifted copy: xsh[m] = xs[m+1]
    unsigned long long* w2 = reinterpret_cast<unsigned long long*>(sm + 2 * XS_HALF); // [8][90]

    const int tid = threadIdx.x;
    const int bx = blockIdx.x;       // 0..3   tile col
    const int by = blockIdx.y;       // 0..15  tile row
    const int bz = blockIdx.z;       // b*4 + og
    const int b  = bz >> 2;
    const int og = bz & 3;           // group of 8 output channels

    const int j0 = bx * TW;
    const int i0 = by * TH;

    // ---- stage weights for this og: only kernel[o][0][...] matters ----
    const float* kb = ker + (og * 8) * (16 * 81);
    for (int idx = tid; idx < 8 * 81; idx += NTHREADS) {
        int o = idx / 81;
        int k = idx - o * 81;
        int a = k / 9;
        int t = k - a * 9;
        float w = kb[o * (16 * 81) + k];
        unsigned int wi = __float_as_uint(w);
        unsigned long long p;
        asm("mov.b64 %0, {%1, %1};" : "=l"(p) : "r"(wi));
        w2[o * 90 + a * 10 + t] = p;
    }

    const int tx   = tid & 15;       // pixel-pair index
    const int ty   = tid >> 4;       // output row within tile
    const int colb = 2 * tx;

    unsigned long long acc[8];
    #pragma unroll
    for (int o = 0; o < 8; ++o) acc[o] = 0ull;

    const float* xb = x + b * (16 * 128 * 128);

    for (int half = 0; half < 2; ++half) {
        if (half) __syncthreads();   // previous compute done before overwrite

        // ---- stage 8 channels (halo, circular wrap), plain + shifted ----
        const float* xbh = xb + half * (8 * 128 * 128);
        for (int idx = tid; idx < XS_HALF; idx += NTHREADS) {
            int c   = idx / CPLANE;
            int rem = idx - c * CPLANE;
            int r   = rem / XCOLS;
            int m   = rem - r * XCOLS;
            int gr  = (i0 - 3 + r) & 127;
            int gc  = (j0 - 3 + m) & 127;
            float v = xbh[(c * 128 + gr) * 128 + gc];
            xs[idx] = v;
            if (m) xsh[idx - 1] = v;
        }
        __syncthreads();

        for (int cg = 0; cg < 2; ++cg) {           // 4 channels per pass
            unsigned long long cv[8][4];
            #pragma unroll
            for (int o = 0; o < 8; ++o)
                #pragma unroll
                for (int c = 0; c < 4; ++c) cv[o][c] = 0ull;

            const float* xc  = xs  + cg * (4 * CPLANE);
            const float* xcs = xsh + cg * (4 * CPLANE);

            for (int a = 0; a < 9; ++a) {
                const int rowoff = (ty + 8 - a) * XCOLS + colb;
                const float* p0 = xc  + rowoff;
                const float* p1 = xcs + rowoff;
                const unsigned long long* wr = w2 + a * 10;

                #pragma unroll
                for (int t0 = 0; t0 < 8; t0 += 2) {    // taps t0 (even), t0+1 (odd)
                    unsigned long long x0[4], x1[4];
                    #pragma unroll
                    for (int c = 0; c < 4; ++c) {
                        // even tap pair from plain copy, odd from shifted copy
                        x0[c] = *reinterpret_cast<const unsigned long long*>(p0 + c * CPLANE + (8 - t0));
                        x1[c] = *reinterpret_cast<const unsigned long long*>(p1 + c * CPLANE + (6 - t0));
                    }
                    #pragma unroll
                    for (int o = 0; o < 8; ++o) {
                        ulonglong2 w01 = *reinterpret_cast<const ulonglong2*>(wr + o * 90 + t0);
                        #pragma unroll
                        for (int c = 0; c < 4; ++c) {
                            ffma2(cv[o][c], x0[c], w01.x);
                            ffma2(cv[o][c], x1[c], w01.y);
                        }
                    }
                }
                {   // tap t = 8 (even)
                    unsigned long long x0[4];
                    #pragma unroll
                    for (int c = 0; c < 4; ++c)
                        x0[c] = *reinterpret_cast<const unsigned long long*>(p0 + c * CPLANE);
                    #pragma unroll
                    for (int o = 0; o < 8; ++o) {
                        unsigned long long w8 = wr[o * 90 + 8];
                        #pragma unroll
                        for (int c = 0; c < 4; ++c) ffma2(cv[o][c], x0[c], w8);
                    }
                }
            }

            // |field| summed over the 4 channels of this group
            #pragma unroll
            for (int o = 0; o < 8; ++o)
                #pragma unroll
                for (int c = 0; c < 4; ++c)
                    acc[o] = fadd2(acc[o], cv[o][c] & 0x7FFFFFFF7FFFFFFFull);
        }
    }

    // ---- store: out[b, og*8+o, i0+ty, j0+colb .. +1] ----
    const int i = i0 + ty;
    const int j = j0 + colb;
    float* ob = out + ((b * 32 + og * 8) * 128 + i) * 128 + j;
    #pragma unroll
    for (int o = 0; o < 8; ++o)
        *reinterpret_cast<unsigned long long*>(ob + o * (128 * 128)) = acc[o];
}

extern "C" void kernel_launch(void* const* d_in, const int* in_sizes, int n_in,
                              void* d_out, int out_size) {
    const float* x   = (const float*)d_in[0];   // [8,16,128,128]
    const float* ker = (const float*)d_in[1];   // [32,16,9,9]
    float* out = (float*)d_out;                 // [8,32,128,128]
    (void)in_sizes; (void)n_in; (void)out_size;

    cudaFuncSetAttribute(optical_conv_kernel,
                         cudaFuncAttributeMaxDynamicSharedMemorySize, SMEM_BYTES);

    dim3 grid(4, 16, 32);   // 4 col-tiles, 16 row-tiles, 8 batch * 4 o-groups
    optical_conv_kernel<<<grid, NTHREADS, SMEM_BYTES>>>(x, ker, out);
}